// round 7
// baseline (speedup 1.0000x reference)
#include <cuda_runtime.h>

#define N_NODES 50000
#define N_EDGES 640000
#define IN_DIM 128
#define HID 128
#define G_OUT 128
#define AX_IN 64
#define AX_OUT 64
#define OUT_CH 8
#define N_GRAPHS 512

// ---------------- scratch (device globals; no allocation) ----------------
__device__ float g_deg[N_NODES];
__device__ float g_dinv[N_NODES];
__device__ float g_H[N_NODES * HID];     // GEMM output (per layer)
__device__ float g_ACC[N_NODES * HID];   // scatter accumulator (per layer)
__device__ float g_sums[N_GRAPHS * HID];
__device__ float g_cnts[N_GRAPHS];

// ---------------- init: deg=1 (self loop), sums=0, cnts=0 ----------------
__global__ void init_kernel() {
    int i = blockIdx.x * blockDim.x + threadIdx.x;
    if (i < N_NODES) g_deg[i] = 1.0f;
    if (i < N_GRAPHS * HID) g_sums[i] = 0.0f;
    if (i < N_GRAPHS) g_cnts[i] = 0.0f;
}

// ---------------- degree count over dst ----------------
__global__ void count_deg_kernel(const int* __restrict__ ei) {
    int e = blockIdx.x * blockDim.x + threadIdx.x;
    if (e >= N_EDGES) return;
    int d = ei[N_EDGES + e];
    atomicAdd(&g_deg[d], 1.0f);   // return unused -> REDG
}

__global__ void dinv_kernel() {
    int i = blockIdx.x * blockDim.x + threadIdx.x;
    if (i >= N_NODES) return;
    g_dinv[i] = rsqrtf(g_deg[i]);   // deg >= 1 always (self loop)
}

// ---------------- dense GEMM + fused self-loop/bias epilogue --------------
// H[N,128] = f(X)[N,128] @ W[128,128]
// ACC[N,128] = b + dinv^2 * H   (self-loop term; scatter adds the rest)
// 64x128 output tile per block, 256 threads, each thread 8x4 micro-tile.
// In-place safe for X==ACC: a block only reads its own output rows, and all
// reads complete before the epilogue stores.
template <bool RELU>
__global__ void gemm_kernel(const float* __restrict__ X,
                            const float* __restrict__ W,
                            const float* __restrict__ b,
                            float* __restrict__ H,
                            float* __restrict__ ACC) {
    __shared__ float Xs[64][17];
    __shared__ float Ws[16][128];
    int tid = threadIdx.x;          // 0..255
    int tx = tid & 31;              // col group: cols [tx*4, tx*4+4)
    int ty = tid >> 5;              // row group: rows [ty*8, ty*8+8)
    int row0 = blockIdx.x * 64;

    float acc[8][4];
#pragma unroll
    for (int i = 0; i < 8; i++)
#pragma unroll
        for (int j = 0; j < 4; j++) acc[i][j] = 0.0f;

    for (int k0 = 0; k0 < 128; k0 += 16) {
        // stage X tile 64x16
#pragma unroll
        for (int l = 0; l < 4; l++) {
            int flat = l * 256 + tid;
            int r = flat >> 4, kk = flat & 15;
            int gr = row0 + r;
            float v = (gr < N_NODES) ? X[gr * 128 + k0 + kk] : 0.0f;
            if (RELU) v = fmaxf(v, 0.0f);
            Xs[r][kk] = v;
        }
        // stage W tile 16x128
#pragma unroll
        for (int l = 0; l < 8; l++) {
            int flat = l * 256 + tid;
            int kk = flat >> 7, j = flat & 127;
            Ws[kk][j] = W[(k0 + kk) * 128 + j];
        }
        __syncthreads();
#pragma unroll
        for (int kk = 0; kk < 16; kk++) {
            float4 wv = *(const float4*)&Ws[kk][tx * 4];
#pragma unroll
            for (int i = 0; i < 8; i++) {
                float xv = Xs[ty * 8 + i][kk];
                acc[i][0] += xv * wv.x;
                acc[i][1] += xv * wv.y;
                acc[i][2] += xv * wv.z;
                acc[i][3] += xv * wv.w;
            }
        }
        __syncthreads();
    }

    float4 bv = *(const float4*)&b[tx * 4];
#pragma unroll
    for (int i = 0; i < 8; i++) {
        int gr = row0 + ty * 8 + i;
        if (gr < N_NODES) {
            float di = g_dinv[gr];
            float s = di * di;
            float4 v = make_float4(acc[i][0], acc[i][1], acc[i][2], acc[i][3]);
            *(float4*)&H[gr * 128 + tx * 4] = v;
            float4 a = make_float4(bv.x + s * v.x, bv.y + s * v.y,
                                   bv.z + s * v.z, bv.w + s * v.w);
            *(float4*)&ACC[gr * 128 + tx * 4] = a;
        }
    }
}

// ---------------- edge scatter: ACC[dst] += H[src] * dinv[s]*dinv[d] ------
// one warp per edge; lane handles 4 contiguous floats (scalar REDG x4)
__global__ void scatter_kernel(const int* __restrict__ ei,
                               const float* __restrict__ H,
                               float* __restrict__ ACC) {
    int warp = (blockIdx.x * blockDim.x + threadIdx.x) >> 5;
    int lane = threadIdx.x & 31;
    if (warp >= N_EDGES) return;
    int s = ei[warp];
    int d = ei[N_EDGES + warp];
    float w = g_dinv[s] * g_dinv[d];
    float4 hv = *(const float4*)&H[s * 128 + lane * 4];
    float* out = &ACC[d * 128 + lane * 4];
    atomicAdd(out + 0, hv.x * w);
    atomicAdd(out + 1, hv.y * w);
    atomicAdd(out + 2, hv.z * w);
    atomicAdd(out + 3, hv.w * w);
}

// ---------------- pooling: sums[batch[i]] += relu(ACC[i]); cnts++ ---------
__global__ void pool_kernel(const float* __restrict__ ACC,
                            const int* __restrict__ batch) {
    int idx = blockIdx.x * blockDim.x + threadIdx.x;  // node*32 + group
    int i = idx >> 5;
    if (i >= N_NODES) return;
    int c = (idx & 31) * 4;
    int g = batch[i];
    float4 v = *(const float4*)&ACC[i * 128 + c];
    float* out = &g_sums[g * 128 + c];
    atomicAdd(out + 0, fmaxf(v.x, 0.0f));
    atomicAdd(out + 1, fmaxf(v.y, 0.0f));
    atomicAdd(out + 2, fmaxf(v.z, 0.0f));
    atomicAdd(out + 3, fmaxf(v.w, 0.0f));
    if ((idx & 31) == 0) atomicAdd(&g_cnts[g], 1.0f);
}

// ---------------- head MLP: one block per graph ---------------------------
__global__ void head_kernel(const float* __restrict__ ax,
                            const float* __restrict__ l1W, const float* __restrict__ l1b,
                            const float* __restrict__ axW, const float* __restrict__ axb,
                            const float* __restrict__ l2W, const float* __restrict__ l2b,
                            float* __restrict__ out) {
    __shared__ float pooled[128];
    __shared__ float z[192];
    int g = blockIdx.x;
    int t = threadIdx.x;  // 0..127
    float cnt = fmaxf(g_cnts[g], 1.0f);
    pooled[t] = g_sums[g * 128 + t] / cnt;
    __syncthreads();

    // g = pooled @ lin1_W + lin1_b   (z[0:128])
    float acc = l1b[t];
#pragma unroll 8
    for (int k = 0; k < 128; k++) acc += pooled[k] * l1W[k * 128 + t];
    z[t] = acc;

    // a = ax @ ax_W + ax_b   (z[128:192])
    if (t < 64) {
        float a = axb[t];
#pragma unroll 8
        for (int k = 0; k < 64; k++) a += ax[g * 64 + k] * axW[k * 64 + t];
        z[128 + t] = a;
    }
    __syncthreads();

    if (t < 8) {
        float o = l2b[t];
#pragma unroll 8
        for (int k = 0; k < 192; k++) o += z[k] * l2W[k * 8 + t];
        out[g * 8 + t] = o;
    }
}

// ---------------- launch --------------------------------------------------
extern "C" void kernel_launch(void* const* d_in, const int* in_sizes, int n_in,
                              void* d_out, int out_size) {
    const float* x = (const float*)d_in[0];
    const int* ei = (const int*)d_in[1];       // int32 per harness dtype table
    const int* batch = (const int*)d_in[2];    // int32 per harness dtype table
    const float* ax = (const float*)d_in[3];
    const float* W1 = (const float*)d_in[4];
    const float* b1 = (const float*)d_in[5];
    const float* W2 = (const float*)d_in[6];
    const float* b2 = (const float*)d_in[7];
    const float* l1W = (const float*)d_in[8];
    const float* l1b = (const float*)d_in[9];
    const float* axW = (const float*)d_in[10];
    const float* axb = (const float*)d_in[11];
    const float* l2W = (const float*)d_in[12];
    const float* l2b = (const float*)d_in[13];
    float* out = (float*)d_out;

    float *dH, *dACC;
    cudaGetSymbolAddress((void**)&dH, g_H);
    cudaGetSymbolAddress((void**)&dACC, g_ACC);

    // 1. init deg/sums/cnts
    init_kernel<<<(N_GRAPHS * HID + 255) / 256, 256>>>();
    // 2. degree + norm
    count_deg_kernel<<<(N_EDGES + 255) / 256, 256>>>(ei);
    dinv_kernel<<<(N_NODES + 255) / 256, 256>>>();

    // ---- layer 1 ----
    gemm_kernel<false><<<(N_NODES + 63) / 64, 256>>>(x, W1, b1, dH, dACC);
    scatter_kernel<<<(N_EDGES * 32 + 255) / 256, 256>>>(ei, dH, dACC);

    // ---- layer 2 (relu applied on GEMM input load; ACC updated in place) ----
    gemm_kernel<true><<<(N_NODES + 63) / 64, 256>>>(dACC, W2, b2, dH, dACC);
    scatter_kernel<<<(N_EDGES * 32 + 255) / 256, 256>>>(ei, dH, dACC);

    // ---- pooling (relu applied here) ----
    pool_kernel<<<(N_NODES * 32 + 255) / 256, 256>>>(dACC, batch);

    // ---- head MLP ----
    head_kernel<<<N_GRAPHS, 128>>>(ax, l1W, l1b, axW, axb, l2W, l2b, out);
}

// round 8
// speedup vs baseline: 1.6355x; 1.6355x over previous
#include <cuda_runtime.h>

#define N_NODES 50000
#define N_EDGES 640000
#define IN_DIM 128
#define HID 128
#define G_OUT 128
#define AX_IN 64
#define AX_OUT 64
#define OUT_CH 8
#define N_GRAPHS 512

// ---------------- scratch (device globals; no allocation) ----------------
__device__ int   g_deg_i[N_NODES];        // in-degree (dst), excl. self loop
__device__ int   g_rowptr[N_NODES];       // CSR row start (by dst)
__device__ int   g_cursor[N_NODES];       // fill cursor
__device__ int   g_csr_src[N_EDGES];      // src node id, grouped by dst
__device__ float g_dinv[N_NODES];
__device__ float g_H[N_NODES * HID];      // GEMM output (per layer)
__device__ float g_ACC[N_NODES * HID];    // aggregated output (per layer)
__device__ float g_sums[N_GRAPHS * HID];
__device__ float g_cnts[N_GRAPHS];

// ---------------- init: deg=0, sums=0, cnts=0 ----------------
__global__ void init_kernel() {
    int i = blockIdx.x * blockDim.x + threadIdx.x;
    if (i < N_NODES) g_deg_i[i] = 0;
    if (i < N_GRAPHS * HID) g_sums[i] = 0.0f;
    if (i < N_GRAPHS) g_cnts[i] = 0.0f;
}

// ---------------- degree count over dst (int histogram) ----------------
__global__ void count_deg_kernel(const int* __restrict__ ei) {
    int e = blockIdx.x * blockDim.x + threadIdx.x;
    if (e >= N_EDGES) return;
    atomicAdd(&g_deg_i[ei[N_EDGES + e]], 1);   // REDG int
}

// ---------------- dinv = rsqrt(1 + deg)  (self loop adds 1) ----------------
__global__ void dinv_kernel() {
    int i = blockIdx.x * blockDim.x + threadIdx.x;
    if (i >= N_NODES) return;
    g_dinv[i] = rsqrtf(1.0f + (float)g_deg_i[i]);
}

// ---------------- exclusive scan of degrees -> rowptr, cursor -------------
// single block, 1024 threads, each owns ceil(N/1024) contiguous items
__global__ void scan_kernel() {
    __shared__ int partial[1024];
    const int ITEMS = (N_NODES + 1023) / 1024;   // 49
    int t = threadIdx.x;
    int base = t * ITEMS;
    int sum = 0;
    for (int i = 0; i < ITEMS; i++) {
        int idx = base + i;
        if (idx < N_NODES) sum += g_deg_i[idx];
    }
    partial[t] = sum;
    __syncthreads();
    // Hillis-Steele inclusive scan over 1024 partials
    for (int off = 1; off < 1024; off <<= 1) {
        int v = 0;
        if (t >= off) v = partial[t - off];
        __syncthreads();
        if (t >= off) partial[t] += v;
        __syncthreads();
    }
    int run = (t > 0) ? partial[t - 1] : 0;  // exclusive prefix for this chunk
    for (int i = 0; i < ITEMS; i++) {
        int idx = base + i;
        if (idx < N_NODES) {
            g_rowptr[idx] = run;
            g_cursor[idx] = run;
            run += g_deg_i[idx];
        }
    }
}

// ---------------- fill CSR: bucket src ids by dst ----------------
__global__ void fill_kernel(const int* __restrict__ ei) {
    int e = blockIdx.x * blockDim.x + threadIdx.x;
    if (e >= N_EDGES) return;
    int s = ei[e];
    int d = ei[N_EDGES + e];
    int p = atomicAdd(&g_cursor[d], 1);
    g_csr_src[p] = s;
}

// ---------------- dense GEMM: H[N,128] = f(X)[N,128] @ W[128,128] ----------
// 64x128 output tile per block, 256 threads, each thread 8x4 micro-tile.
template <bool RELU>
__global__ void gemm_kernel(const float* __restrict__ X,
                            const float* __restrict__ W,
                            float* __restrict__ H) {
    __shared__ float Xs[64][17];
    __shared__ float Ws[16][128];
    int tid = threadIdx.x;          // 0..255
    int tx = tid & 31;              // col group: cols [tx*4, tx*4+4)
    int ty = tid >> 5;              // row group: rows [ty*8, ty*8+8)
    int row0 = blockIdx.x * 64;

    float acc[8][4];
#pragma unroll
    for (int i = 0; i < 8; i++)
#pragma unroll
        for (int j = 0; j < 4; j++) acc[i][j] = 0.0f;

    for (int k0 = 0; k0 < 128; k0 += 16) {
#pragma unroll
        for (int l = 0; l < 4; l++) {
            int flat = l * 256 + tid;
            int r = flat >> 4, kk = flat & 15;
            int gr = row0 + r;
            float v = (gr < N_NODES) ? X[gr * 128 + k0 + kk] : 0.0f;
            if (RELU) v = fmaxf(v, 0.0f);
            Xs[r][kk] = v;
        }
#pragma unroll
        for (int l = 0; l < 8; l++) {
            int flat = l * 256 + tid;
            int kk = flat >> 7, j = flat & 127;
            Ws[kk][j] = W[(k0 + kk) * 128 + j];
        }
        __syncthreads();
#pragma unroll
        for (int kk = 0; kk < 16; kk++) {
            float4 wv = *(const float4*)&Ws[kk][tx * 4];
#pragma unroll
            for (int i = 0; i < 8; i++) {
                float xv = Xs[ty * 8 + i][kk];
                acc[i][0] += xv * wv.x;
                acc[i][1] += xv * wv.y;
                acc[i][2] += xv * wv.z;
                acc[i][3] += xv * wv.w;
            }
        }
        __syncthreads();
    }
#pragma unroll
    for (int i = 0; i < 8; i++) {
        int gr = row0 + ty * 8 + i;
        if (gr < N_NODES) {
            float4 v = make_float4(acc[i][0], acc[i][1], acc[i][2], acc[i][3]);
            *(float4*)&H[gr * 128 + tx * 4] = v;
        }
    }
}

// ---------------- gather aggregation (atomic-free) -------------------------
// one warp per dst node; lane owns 4 contiguous floats
// ACC[d] = b + dinv[d]^2 * H[d] + sum_{s in N(d)} dinv[s]*dinv[d] * H[s]
__global__ void gather_kernel(const float* __restrict__ H,
                              const float* __restrict__ b,
                              float* __restrict__ ACC) {
    int warp = (blockIdx.x * blockDim.x + threadIdx.x) >> 5;
    int lane = threadIdx.x & 31;
    if (warp >= N_NODES) return;
    int d = warp;
    float dv = g_dinv[d];
    int start = g_rowptr[d];
    int deg = g_deg_i[d];

    float4 bv = *(const float4*)&b[lane * 4];
    float4 hv = *(const float4*)&H[d * 128 + lane * 4];
    float s2 = dv * dv;
    float a0 = bv.x + s2 * hv.x;
    float a1 = bv.y + s2 * hv.y;
    float a2 = bv.z + s2 * hv.z;
    float a3 = bv.w + s2 * hv.w;

    int k = 0;
    for (; k + 2 <= deg; k += 2) {   // unroll x2 for load-latency overlap
        int s0 = g_csr_src[start + k];
        int s1 = g_csr_src[start + k + 1];
        float w0 = dv * g_dinv[s0];
        float w1 = dv * g_dinv[s1];
        float4 h0 = *(const float4*)&H[s0 * 128 + lane * 4];
        float4 h1 = *(const float4*)&H[s1 * 128 + lane * 4];
        a0 += w0 * h0.x + w1 * h1.x;
        a1 += w0 * h0.y + w1 * h1.y;
        a2 += w0 * h0.z + w1 * h1.z;
        a3 += w0 * h0.w + w1 * h1.w;
    }
    if (k < deg) {
        int s0 = g_csr_src[start + k];
        float w0 = dv * g_dinv[s0];
        float4 h0 = *(const float4*)&H[s0 * 128 + lane * 4];
        a0 += w0 * h0.x; a1 += w0 * h0.y; a2 += w0 * h0.z; a3 += w0 * h0.w;
    }
    *(float4*)&ACC[d * 128 + lane * 4] = make_float4(a0, a1, a2, a3);
}

// ---------------- pooling: sums[batch[i]] += relu(ACC[i]); cnts++ ---------
__global__ void pool_kernel(const float* __restrict__ ACC,
                            const int* __restrict__ batch) {
    int idx = blockIdx.x * blockDim.x + threadIdx.x;  // node*32 + group
    int i = idx >> 5;
    if (i >= N_NODES) return;
    int c = (idx & 31) * 4;
    int g = batch[i];
    float4 v = *(const float4*)&ACC[i * 128 + c];
    float* out = &g_sums[g * 128 + c];
    atomicAdd(out + 0, fmaxf(v.x, 0.0f));
    atomicAdd(out + 1, fmaxf(v.y, 0.0f));
    atomicAdd(out + 2, fmaxf(v.z, 0.0f));
    atomicAdd(out + 3, fmaxf(v.w, 0.0f));
    if ((idx & 31) == 0) atomicAdd(&g_cnts[g], 1.0f);
}

// ---------------- head MLP: one block per graph ---------------------------
__global__ void head_kernel(const float* __restrict__ ax,
                            const float* __restrict__ l1W, const float* __restrict__ l1b,
                            const float* __restrict__ axW, const float* __restrict__ axb,
                            const float* __restrict__ l2W, const float* __restrict__ l2b,
                            float* __restrict__ out) {
    __shared__ float pooled[128];
    __shared__ float z[192];
    int g = blockIdx.x;
    int t = threadIdx.x;  // 0..127
    float cnt = fmaxf(g_cnts[g], 1.0f);
    pooled[t] = g_sums[g * 128 + t] / cnt;
    __syncthreads();

    float acc = l1b[t];
#pragma unroll 8
    for (int k = 0; k < 128; k++) acc += pooled[k] * l1W[k * 128 + t];
    z[t] = acc;

    if (t < 64) {
        float a = axb[t];
#pragma unroll 8
        for (int k = 0; k < 64; k++) a += ax[g * 64 + k] * axW[k * 64 + t];
        z[128 + t] = a;
    }
    __syncthreads();

    if (t < 8) {
        float o = l2b[t];
#pragma unroll 8
        for (int k = 0; k < 192; k++) o += z[k] * l2W[k * 8 + t];
        out[g * 8 + t] = o;
    }
}

// ---------------- launch --------------------------------------------------
extern "C" void kernel_launch(void* const* d_in, const int* in_sizes, int n_in,
                              void* d_out, int out_size) {
    const float* x = (const float*)d_in[0];
    const int* ei = (const int*)d_in[1];
    const int* batch = (const int*)d_in[2];
    const float* ax = (const float*)d_in[3];
    const float* W1 = (const float*)d_in[4];
    const float* b1 = (const float*)d_in[5];
    const float* W2 = (const float*)d_in[6];
    const float* b2 = (const float*)d_in[7];
    const float* l1W = (const float*)d_in[8];
    const float* l1b = (const float*)d_in[9];
    const float* axW = (const float*)d_in[10];
    const float* axb = (const float*)d_in[11];
    const float* l2W = (const float*)d_in[12];
    const float* l2b = (const float*)d_in[13];
    float* out = (float*)d_out;

    float *dH, *dACC;
    cudaGetSymbolAddress((void**)&dH, g_H);
    cudaGetSymbolAddress((void**)&dACC, g_ACC);

    // ---- CSR build ----
    init_kernel<<<(N_GRAPHS * HID + 255) / 256, 256>>>();
    count_deg_kernel<<<(N_EDGES + 255) / 256, 256>>>(ei);
    dinv_kernel<<<(N_NODES + 255) / 256, 256>>>();
    scan_kernel<<<1, 1024>>>();
    fill_kernel<<<(N_EDGES + 255) / 256, 256>>>(ei);

    // ---- layer 1 ----
    gemm_kernel<false><<<(N_NODES + 63) / 64, 256>>>(x, W1, dH);
    gather_kernel<<<(N_NODES * 32 + 255) / 256, 256>>>(dH, b1, dACC);

    // ---- layer 2 (relu applied on GEMM input load) ----
    gemm_kernel<true><<<(N_NODES + 63) / 64, 256>>>(dACC, W2, dH);
    gather_kernel<<<(N_NODES * 32 + 255) / 256, 256>>>(dH, b2, dACC);

    // ---- pooling (relu applied here) ----
    pool_kernel<<<(N_NODES * 32 + 255) / 256, 256>>>(dACC, batch);

    // ---- head MLP ----
    head_kernel<<<N_GRAPHS, 128>>>(ax, l1W, l1b, axW, axb, l2W, l2b, out);
}

// round 9
// speedup vs baseline: 2.1182x; 1.2951x over previous
#include <cuda_runtime.h>

#define N_NODES 50000
#define N_EDGES 640000
#define IN_DIM 128
#define HID 128
#define G_OUT 128
#define AX_IN 64
#define AX_OUT 64
#define OUT_CH 8
#define N_GRAPHS 512

#define SCAN_BLK 49               // ceil(50000/1024)

// ---------------- scratch (device globals; no allocation) ----------------
__device__ int   g_deg_i[N_NODES];        // in-degree (dst), excl. self loop
__device__ int   g_rowptr[N_NODES];       // CSR row start (by dst)
__device__ int   g_cursor[N_NODES];       // fill cursor
__device__ int   g_csr_src[N_EDGES];      // src node id, grouped by dst
__device__ int   g_bsum[SCAN_BLK];        // per-1024-chunk degree sums
__device__ int   g_boff[SCAN_BLK];        // exclusive chunk offsets
__device__ float g_dinv[N_NODES];
__device__ float g_H[N_NODES * HID];      // GEMM output (per layer)
__device__ float g_ACC[N_NODES * HID];    // aggregated output (per layer)
__device__ float g_sums[N_GRAPHS * HID];
__device__ float g_cnts[N_GRAPHS];

// ---------------- init: deg=0, sums=0, cnts=0 ----------------
__global__ void init_kernel() {
    int i = blockIdx.x * blockDim.x + threadIdx.x;
    if (i < N_NODES) g_deg_i[i] = 0;
    if (i < N_GRAPHS * HID) g_sums[i] = 0.0f;
    if (i < N_GRAPHS) g_cnts[i] = 0.0f;
}

// ---------------- degree count over dst (int histogram) ----------------
__global__ void count_deg_kernel(const int* __restrict__ ei) {
    int e = blockIdx.x * blockDim.x + threadIdx.x;
    if (e >= N_EDGES) return;
    atomicAdd(&g_deg_i[ei[N_EDGES + e]], 1);   // REDG int
}

// ---------------- scan phase 1: per-chunk sums (1024 items/block) ---------
__global__ void bsum_kernel() {
    __shared__ int tsum[256];
    int b = blockIdx.x, t = threadIdx.x;
    int base = b * 1024 + t * 4;
    int s = 0;
#pragma unroll
    for (int j = 0; j < 4; j++) {
        int idx = base + j;
        if (idx < N_NODES) s += g_deg_i[idx];
    }
    tsum[t] = s;
    __syncthreads();
    for (int off = 128; off > 0; off >>= 1) {
        if (t < off) tsum[t] += tsum[t + off];
        __syncthreads();
    }
    if (t == 0) g_bsum[b] = tsum[0];
}

// ---------------- scan phase 2: exclusive scan of 49 chunk sums -----------
__global__ void bscan_kernel() {
    __shared__ int v[64];
    int t = threadIdx.x;   // 64 threads
    v[t] = (t < SCAN_BLK) ? g_bsum[t] : 0;
    __syncthreads();
    for (int off = 1; off < 64; off <<= 1) {
        int x = 0;
        if (t >= off) x = v[t - off];
        __syncthreads();
        if (t >= off) v[t] += x;
        __syncthreads();
    }
    if (t < SCAN_BLK) g_boff[t] = (t > 0) ? v[t - 1] : 0;
}

// ---------------- scan phase 3: write rowptr/cursor + dinv ----------------
__global__ void rowptr_kernel() {
    __shared__ int tsum[256];
    int b = blockIdx.x, t = threadIdx.x;
    int base = b * 1024 + t * 4;
    int d[4];
    int s = 0;
#pragma unroll
    for (int j = 0; j < 4; j++) {
        int idx = base + j;
        d[j] = (idx < N_NODES) ? g_deg_i[idx] : 0;
        s += d[j];
    }
    tsum[t] = s;
    __syncthreads();
    for (int off = 1; off < 256; off <<= 1) {
        int x = 0;
        if (t >= off) x = tsum[t - off];
        __syncthreads();
        if (t >= off) tsum[t] += x;
        __syncthreads();
    }
    int run = g_boff[b] + ((t > 0) ? tsum[t - 1] : 0);
#pragma unroll
    for (int j = 0; j < 4; j++) {
        int idx = base + j;
        if (idx < N_NODES) {
            g_rowptr[idx] = run;
            g_cursor[idx] = run;
            run += d[j];
            g_dinv[idx] = rsqrtf(1.0f + (float)d[j]);  // self loop adds 1
        }
    }
}

// ---------------- fill CSR: bucket src ids by dst ----------------
__global__ void fill_kernel(const int* __restrict__ ei) {
    int e = blockIdx.x * blockDim.x + threadIdx.x;
    if (e >= N_EDGES) return;
    int s = ei[e];
    int d = ei[N_EDGES + e];
    int p = atomicAdd(&g_cursor[d], 1);
    g_csr_src[p] = s;
}

// ---------------- dense GEMM: H[N,128] = f(X)[N,128] @ W[128,128] ----------
// 64x128 output tile per block, 256 threads, each thread 8x4 micro-tile.
template <bool RELU>
__global__ void gemm_kernel(const float* __restrict__ X,
                            const float* __restrict__ W,
                            float* __restrict__ H) {
    __shared__ float Xs[64][17];
    __shared__ float Ws[16][128];
    int tid = threadIdx.x;          // 0..255
    int tx = tid & 31;              // col group: cols [tx*4, tx*4+4)
    int ty = tid >> 5;              // row group: rows [ty*8, ty*8+8)
    int row0 = blockIdx.x * 64;

    float acc[8][4];
#pragma unroll
    for (int i = 0; i < 8; i++)
#pragma unroll
        for (int j = 0; j < 4; j++) acc[i][j] = 0.0f;

    for (int k0 = 0; k0 < 128; k0 += 16) {
#pragma unroll
        for (int l = 0; l < 4; l++) {
            int flat = l * 256 + tid;
            int r = flat >> 4, kk = flat & 15;
            int gr = row0 + r;
            float v = (gr < N_NODES) ? X[gr * 128 + k0 + kk] : 0.0f;
            if (RELU) v = fmaxf(v, 0.0f);
            Xs[r][kk] = v;
        }
#pragma unroll
        for (int l = 0; l < 8; l++) {
            int flat = l * 256 + tid;
            int kk = flat >> 7, j = flat & 127;
            Ws[kk][j] = W[(k0 + kk) * 128 + j];
        }
        __syncthreads();
#pragma unroll
        for (int kk = 0; kk < 16; kk++) {
            float4 wv = *(const float4*)&Ws[kk][tx * 4];
#pragma unroll
            for (int i = 0; i < 8; i++) {
                float xv = Xs[ty * 8 + i][kk];
                acc[i][0] += xv * wv.x;
                acc[i][1] += xv * wv.y;
                acc[i][2] += xv * wv.z;
                acc[i][3] += xv * wv.w;
            }
        }
        __syncthreads();
    }
#pragma unroll
    for (int i = 0; i < 8; i++) {
        int gr = row0 + ty * 8 + i;
        if (gr < N_NODES) {
            float4 v = make_float4(acc[i][0], acc[i][1], acc[i][2], acc[i][3]);
            *(float4*)&H[gr * 128 + tx * 4] = v;
        }
    }
}

// ---------------- gather aggregation (atomic-free) -------------------------
// one warp per dst node; lane owns 4 contiguous floats
// ACC[d] = b + dinv[d]^2 * H[d] + sum_{s in N(d)} dinv[s]*dinv[d] * H[s]
__global__ void gather_kernel(const float* __restrict__ H,
                              const float* __restrict__ b,
                              float* __restrict__ ACC) {
    int warp = (blockIdx.x * blockDim.x + threadIdx.x) >> 5;
    int lane = threadIdx.x & 31;
    if (warp >= N_NODES) return;
    int d = warp;
    float dv = g_dinv[d];
    int start = g_rowptr[d];
    int deg = g_deg_i[d];

    float4 bv = *(const float4*)&b[lane * 4];
    float4 hv = *(const float4*)&H[d * 128 + lane * 4];
    float s2 = dv * dv;
    float a0 = bv.x + s2 * hv.x;
    float a1 = bv.y + s2 * hv.y;
    float a2 = bv.z + s2 * hv.z;
    float a3 = bv.w + s2 * hv.w;

    int k = 0;
    for (; k + 2 <= deg; k += 2) {   // unroll x2 for load-latency overlap
        int s0 = g_csr_src[start + k];
        int s1 = g_csr_src[start + k + 1];
        float w0 = dv * g_dinv[s0];
        float w1 = dv * g_dinv[s1];
        float4 h0 = *(const float4*)&H[s0 * 128 + lane * 4];
        float4 h1 = *(const float4*)&H[s1 * 128 + lane * 4];
        a0 += w0 * h0.x + w1 * h1.x;
        a1 += w0 * h0.y + w1 * h1.y;
        a2 += w0 * h0.z + w1 * h1.z;
        a3 += w0 * h0.w + w1 * h1.w;
    }
    if (k < deg) {
        int s0 = g_csr_src[start + k];
        float w0 = dv * g_dinv[s0];
        float4 h0 = *(const float4*)&H[s0 * 128 + lane * 4];
        a0 += w0 * h0.x; a1 += w0 * h0.y; a2 += w0 * h0.z; a3 += w0 * h0.w;
    }
    *(float4*)&ACC[d * 128 + lane * 4] = make_float4(a0, a1, a2, a3);
}

// ---------------- pooling: sums[batch[i]] += relu(ACC[i]); cnts++ ---------
__global__ void pool_kernel(const float* __restrict__ ACC,
                            const int* __restrict__ batch) {
    int idx = blockIdx.x * blockDim.x + threadIdx.x;  // node*32 + group
    int i = idx >> 5;
    if (i >= N_NODES) return;
    int c = (idx & 31) * 4;
    int g = batch[i];
    float4 v = *(const float4*)&ACC[i * 128 + c];
    float* out = &g_sums[g * 128 + c];
    atomicAdd(out + 0, fmaxf(v.x, 0.0f));
    atomicAdd(out + 1, fmaxf(v.y, 0.0f));
    atomicAdd(out + 2, fmaxf(v.z, 0.0f));
    atomicAdd(out + 3, fmaxf(v.w, 0.0f));
    if ((idx & 31) == 0) atomicAdd(&g_cnts[g], 1.0f);
}

// ---------------- head MLP: one block per graph ---------------------------
__global__ void head_kernel(const float* __restrict__ ax,
                            const float* __restrict__ l1W, const float* __restrict__ l1b,
                            const float* __restrict__ axW, const float* __restrict__ axb,
                            const float* __restrict__ l2W, const float* __restrict__ l2b,
                            float* __restrict__ out) {
    __shared__ float pooled[128];
    __shared__ float z[192];
    int g = blockIdx.x;
    int t = threadIdx.x;  // 0..127
    float cnt = fmaxf(g_cnts[g], 1.0f);
    pooled[t] = g_sums[g * 128 + t] / cnt;
    __syncthreads();

    float acc = l1b[t];
#pragma unroll 8
    for (int k = 0; k < 128; k++) acc += pooled[k] * l1W[k * 128 + t];
    z[t] = acc;

    if (t < 64) {
        float a = axb[t];
#pragma unroll 8
        for (int k = 0; k < 64; k++) a += ax[g * 64 + k] * axW[k * 64 + t];
        z[128 + t] = a;
    }
    __syncthreads();

    if (t < 8) {
        float o = l2b[t];
#pragma unroll 8
        for (int k = 0; k < 192; k++) o += z[k] * l2W[k * 8 + t];
        out[g * 8 + t] = o;
    }
}

// ---------------- launch --------------------------------------------------
extern "C" void kernel_launch(void* const* d_in, const int* in_sizes, int n_in,
                              void* d_out, int out_size) {
    const float* x = (const float*)d_in[0];
    const int* ei = (const int*)d_in[1];
    const int* batch = (const int*)d_in[2];
    const float* ax = (const float*)d_in[3];
    const float* W1 = (const float*)d_in[4];
    const float* b1 = (const float*)d_in[5];
    const float* W2 = (const float*)d_in[6];
    const float* b2 = (const float*)d_in[7];
    const float* l1W = (const float*)d_in[8];
    const float* l1b = (const float*)d_in[9];
    const float* axW = (const float*)d_in[10];
    const float* axb = (const float*)d_in[11];
    const float* l2W = (const float*)d_in[12];
    const float* l2b = (const float*)d_in[13];
    float* out = (float*)d_out;

    float *dH, *dACC;
    cudaGetSymbolAddress((void**)&dH, g_H);
    cudaGetSymbolAddress((void**)&dACC, g_ACC);

    // ---- CSR build (parallel 3-phase scan) ----
    init_kernel<<<(N_GRAPHS * HID + 255) / 256, 256>>>();
    count_deg_kernel<<<(N_EDGES + 255) / 256, 256>>>(ei);
    bsum_kernel<<<SCAN_BLK, 256>>>();
    bscan_kernel<<<1, 64>>>();
    rowptr_kernel<<<SCAN_BLK, 256>>>();
    fill_kernel<<<(N_EDGES + 255) / 256, 256>>>(ei);

    // ---- layer 1 ----
    gemm_kernel<false><<<(N_NODES + 63) / 64, 256>>>(x, W1, dH);
    gather_kernel<<<(N_NODES * 32 + 255) / 256, 256>>>(dH, b1, dACC);

    // ---- layer 2 (relu applied on GEMM input load) ----
    gemm_kernel<true><<<(N_NODES + 63) / 64, 256>>>(dACC, W2, dH);
    gather_kernel<<<(N_NODES * 32 + 255) / 256, 256>>>(dH, b2, dACC);

    // ---- pooling (relu applied here) ----
    pool_kernel<<<(N_NODES * 32 + 255) / 256, 256>>>(dACC, batch);

    // ---- head MLP ----
    head_kernel<<<N_GRAPHS, 128>>>(ax, l1W, l1b, axW, axb, l2W, l2b, out);
}